// round 7
// baseline (speedup 1.0000x reference)
#include <cuda_runtime.h>
#include <cuda_fp16.h>
#include <mma.h>
#include <cstdint>

using namespace nvcuda;

#define D_MODEL 2048
#define NUM_EXPERTS 64
#define M_TILE 128
#define KC 64
#define T_CHUNKS (D_MODEL / KC)    // 32
#define NTHREADS 256
#define RS 72                      // row stride (halfs) = 144B : 16 mod 128 -> LDSM conflict-free
#define A_ELTS (M_TILE * RS)       // 9216 halfs per level
#define B_ELTS (NUM_EXPERTS * RS)  // 4608 halfs per level
#define SBUF_ELTS (2 * A_ELTS + 2 * B_ELTS)   // 27648 halfs = 55296 B per stage
#define SMEM_BYTES (2 * SBUF_ELTS * 2)        // 110592 B
#define LSTRIDE 72

// W pre-packed: [chunk][lev][e][64 halfs, k-permuted], dense 128B rows
__device__ __align__(16) __half g_wp[2 * NUM_EXPERTS * D_MODEL];

// k-slot permutation within a 64-k chunk:
//   k <  32 : s = (k>>2)*8 + (k&3)
//   k >= 32 : s = ((k-32)>>2)*8 + 4 + (k&3)
// (A and B both use it, so the MMA sum is order-invariant and correct.)

__global__ void prep_w(const float* __restrict__ w) {
    int i = (blockIdx.x * blockDim.x + threadIdx.x) * 4;   // 4 consecutive k, same 4-block
    float4 v = *reinterpret_cast<const float4*>(w + i);
    float a[4] = {v.x, v.y, v.z, v.w};
    __half h0[4], h1[4];
#pragma unroll
    for (int j = 0; j < 4; j++) {
        __half t0 = __float2half_rn(a[j]);
        h0[j] = t0;
        h1[j] = __float2half_rn(a[j] - __half2float(t0));
    }
    const int e = i / D_MODEL;
    const int k = i % D_MODEL;
    const int c = k >> 6;        // chunk
    const int kk = k & 63;
    const int s = (kk < 32) ? ((kk >> 2) * 8 + (kk & 3))
                            : (((kk - 32) >> 2) * 8 + 4 + (kk & 3));
    __half* d0 = g_wp + ((size_t)(c * 2 + 0) * 64 + e) * 64 + s;
    __half* d1 = g_wp + ((size_t)(c * 2 + 1) * 64 + e) * 64 + s;
    *reinterpret_cast<uint2*>(d0) = *reinterpret_cast<uint2*>(h0);
    *reinterpret_cast<uint2*>(d1) = *reinterpret_cast<uint2*>(h1);
}

__device__ __forceinline__ uint32_t smem_u32(const void* p) {
    uint32_t a;
    asm("{ .reg .u64 t; cvta.to.shared.u64 t, %1; cvt.u32.u64 %0, t; }" : "=r"(a) : "l"(p));
    return a;
}
__device__ __forceinline__ void cp_async16(uint32_t dst, const void* src) {
    asm volatile("cp.async.cg.shared.global [%0], [%1], 16;" :: "r"(dst), "l"(src) : "memory");
}
#define CP_COMMIT() asm volatile("cp.async.commit_group;" ::: "memory")
#define CP_WAIT0()  asm volatile("cp.async.wait_group 0;" ::: "memory")

__global__ void __launch_bounds__(NTHREADS, 2) router_hsplit(
    const float* __restrict__ x,
    const float* __restrict__ bias,
    float* __restrict__ out,
    int n_rows)
{
    extern __shared__ __align__(16) __half smem[];

    const int tid = threadIdx.x;
    const int wid = tid >> 5;
    const int wm = wid & 3;
    const int wn = wid >> 2;
    const long long row0 = (long long)blockIdx.x * M_TILE;

    // x loader: row = (tid>>3) + 32*i, cols c=(tid&7)*4 and c+32 (float4 each)
    const int xr = tid >> 3;
    const int xc = (tid & 7) * 4;

    const float* xb = x + row0 * D_MODEL;

    wmma::fragment<wmma::accumulator, 16, 16, 16, float> acc[2][2];
#pragma unroll
    for (int mt = 0; mt < 2; mt++)
#pragma unroll
        for (int nt = 0; nt < 2; nt++) wmma::fill_fragment(acc[mt][nt], 0.0f);

    float4 xv[8];

    auto loadg = [&](int c, int buf) {
        const int k0 = c * KC;
#pragma unroll
        for (int i = 0; i < 4; i++) {
            const float* xp = xb + (long long)(xr + 32 * i) * D_MODEL + k0;
            xv[2 * i]     = *reinterpret_cast<const float4*>(xp + xc);
            xv[2 * i + 1] = *reinterpret_cast<const float4*>(xp + xc + 32);
        }
        // W tiles via cp.async: 128 rows (64e x 2lev) of 128B, dense -> stride-72 smem
        __half* Bb = smem + buf * SBUF_ELTS + 2 * A_ELTS;
        const __half* ws = g_wp + (size_t)c * 2 * NUM_EXPERTS * KC;
        const int rr = tid >> 3;            // 0..31, sweeps +32
        const int seg = (tid & 7) * 8;      // 16B segment (halfs)
#pragma unroll
        for (int i = 0; i < 4; i++) {
            const int row = rr + 32 * i;    // row = lev*64 + e
            const int lev = row >> 6;
            const int e = row & 63;
            uint32_t dst = smem_u32(Bb + lev * B_ELTS + e * RS + seg);
            cp_async16(dst, ws + row * 64 + seg);
        }
        CP_COMMIT();
    };

    auto stores = [&](int buf) {
        __half* A0 = smem + buf * SBUF_ELTS;
        __half* A1 = A0 + A_ELTS;
#pragma unroll
        for (int i = 0; i < 4; i++) {
            float4 u = xv[2 * i], v = xv[2 * i + 1];
            // level 0
            __half2 p0 = __floats2half2_rn(u.x, u.y);
            __half2 p1 = __floats2half2_rn(u.z, u.w);
            __half2 p2 = __floats2half2_rn(v.x, v.y);
            __half2 p3 = __floats2half2_rn(v.z, v.w);
            // residuals
            float r0 = u.x - __half2float(p0.x), r1 = u.y - __half2float(p0.y);
            float r2 = u.z - __half2float(p1.x), r3 = u.w - __half2float(p1.y);
            float r4 = v.x - __half2float(p2.x), r5 = v.y - __half2float(p2.y);
            float r6 = v.z - __half2float(p3.x), r7 = v.w - __half2float(p3.y);
            __half2 q0 = __floats2half2_rn(r0, r1);
            __half2 q1 = __floats2half2_rn(r2, r3);
            __half2 q2 = __floats2half2_rn(r4, r5);
            __half2 q3 = __floats2half2_rn(r6, r7);

            // slots 2*xc .. 2*xc+7  (k-permuted contiguous)
            const int o = (xr + 32 * i) * RS + 2 * xc;
            uint4 s0 = make_uint4(*reinterpret_cast<uint32_t*>(&p0), *reinterpret_cast<uint32_t*>(&p1),
                                  *reinterpret_cast<uint32_t*>(&p2), *reinterpret_cast<uint32_t*>(&p3));
            uint4 s1 = make_uint4(*reinterpret_cast<uint32_t*>(&q0), *reinterpret_cast<uint32_t*>(&q1),
                                  *reinterpret_cast<uint32_t*>(&q2), *reinterpret_cast<uint32_t*>(&q3));
            *reinterpret_cast<uint4*>(A0 + o) = s0;
            *reinterpret_cast<uint4*>(A1 + o) = s1;
        }
    };

    auto compute = [&](int buf) {
        const __half* A0 = smem + buf * SBUF_ELTS;
        const __half* A1 = A0 + A_ELTS;
        const __half* B0 = A0 + 2 * A_ELTS;
        const __half* B1 = B0 + B_ELTS;
#pragma unroll
        for (int ks = 0; ks < KC; ks += 16) {
            wmma::fragment<wmma::matrix_a, 16, 16, 16, __half, wmma::row_major> a0f[2], a1f[2];
            wmma::fragment<wmma::matrix_b, 16, 16, 16, __half, wmma::col_major> b0f[2], b1f[2];
#pragma unroll
            for (int mt = 0; mt < 2; mt++) {
                const int ro = (32 * wm + 16 * mt) * RS + ks;
                wmma::load_matrix_sync(a0f[mt], A0 + ro, RS);
                wmma::load_matrix_sync(a1f[mt], A1 + ro, RS);
            }
#pragma unroll
            for (int nt = 0; nt < 2; nt++) {
                const int co = (32 * wn + 16 * nt) * RS + ks;
                wmma::load_matrix_sync(b0f[nt], B0 + co, RS);
                wmma::load_matrix_sync(b1f[nt], B1 + co, RS);
            }
#pragma unroll
            for (int mt = 0; mt < 2; mt++)
#pragma unroll
                for (int nt = 0; nt < 2; nt++)
                    wmma::mma_sync(acc[mt][nt], a0f[mt], b0f[nt], acc[mt][nt]);
#pragma unroll
            for (int mt = 0; mt < 2; mt++)
#pragma unroll
                for (int nt = 0; nt < 2; nt++)
                    wmma::mma_sync(acc[mt][nt], a0f[mt], b1f[nt], acc[mt][nt]);
#pragma unroll
            for (int mt = 0; mt < 2; mt++)
#pragma unroll
                for (int nt = 0; nt < 2; nt++)
                    wmma::mma_sync(acc[mt][nt], a1f[mt], b0f[nt], acc[mt][nt]);
        }
    };

    // ---- prologue ----
    loadg(0, 0);
    stores(0);
    CP_WAIT0();
    __syncthreads();

#pragma unroll 1
    for (int c = 0; c < T_CHUNKS; ++c) {
        if (c + 1 < T_CHUNKS) loadg(c + 1, (c + 1) & 1);
        compute(c & 1);
        if (c + 1 < T_CHUNKS) stores((c + 1) & 1);
        CP_WAIT0();
        __syncthreads();
    }

    // ---- epilogue ----
    float* logits = reinterpret_cast<float*>(smem);
#pragma unroll
    for (int mt = 0; mt < 2; mt++)
#pragma unroll
        for (int nt = 0; nt < 2; nt++)
            wmma::store_matrix_sync(
                logits + (32 * wm + 16 * mt) * LSTRIDE + 32 * wn + 16 * nt,
                acc[mt][nt], LSTRIDE, wmma::mem_row_major);
    __syncthreads();

    if (tid < M_TILE) {
        const int r = tid;
        const float* lrow = logits + r * LSTRIDE;
        float v0 = -3.0e38f, v1 = -3.0e38f;
        int i0 = 0, i1 = 0;
#pragma unroll
        for (int e = 0; e < NUM_EXPERTS; e++) {
            float l = lrow[e] + __ldg(&bias[e]);
            if (l > v0) { v1 = v0; i1 = i0; v0 = l; i0 = e; }
            else if (l > v1) { v1 = l; i1 = e; }
        }
        float Z = 0.0f;
#pragma unroll
        for (int e = 0; e < NUM_EXPERTS; e++) {
            float l = lrow[e] + __ldg(&bias[e]);
            Z += __expf(l - v0);
        }
        float q0 = 1.0f / Z;
        float q1 = __expf(v1 - v0) / Z;
        float s = q0 + q1 + 1e-8f;
        long long gr = row0 + r;
        out[gr * 2 + 0] = q0 / s;
        out[gr * 2 + 1] = q1 / s;
        float* ido = out + (long long)n_rows * 2;
        ido[gr * 2 + 0] = (float)i0;
        ido[gr * 2 + 1] = (float)i1;
    }
}

extern "C" void kernel_launch(void* const* d_in, const int* in_sizes, int n_in,
                              void* d_out, int out_size) {
    const float* x    = (const float*)d_in[0];
    const float* gw   = (const float*)d_in[1];
    const float* bias = (const float*)d_in[2];
    float* out = (float*)d_out;
    int n_rows = in_sizes[0] / D_MODEL;   // 32768

    cudaFuncSetAttribute(router_hsplit, cudaFuncAttributeMaxDynamicSharedMemorySize, SMEM_BYTES);

    prep_w<<<(NUM_EXPERTS * D_MODEL / 4) / 256, 256>>>(gw);
    router_hsplit<<<n_rows / M_TILE, NTHREADS, SMEM_BYTES>>>(x, bias, out, n_rows);
}

// round 8
// speedup vs baseline: 1.0095x; 1.0095x over previous
#include <cuda_runtime.h>
#include <cuda_fp16.h>
#include <mma.h>
#include <cstdint>

using namespace nvcuda;

#define D_MODEL 2048
#define NUM_EXPERTS 64
#define M_TILE 128
#define KC 32
#define T_CHUNKS (D_MODEL / KC)    // 64
#define NTHREADS 256
#define AS 40                      // A row stride (halfs) = 80B, LDSM conflict-free
#define WS 40                      // B row stride (halfs)
#define A_ELTS (M_TILE * AS)       // 5120
#define B_ELTS (NUM_EXPERTS * WS)  // 2560
#define SBUF_ELTS (2 * A_ELTS + 2 * B_ELTS)   // 15360 halfs
#define SMEM_BYTES (2 * SBUF_ELTS * 2)        // 61440 B
#define LSTRIDE 72

// W pre-packed chunk-contiguous: [chunk][lev][e][32 halfs]
__device__ __align__(16) __half g_wp[2 * NUM_EXPERTS * D_MODEL];

__global__ void prep_w(const float* __restrict__ w) {
    int i = (blockIdx.x * blockDim.x + threadIdx.x) * 4;
    float4 v = *reinterpret_cast<const float4*>(w + i);
    float a[4] = {v.x, v.y, v.z, v.w};
    __half h0[4], h1[4];
#pragma unroll
    for (int j = 0; j < 4; j++) {
        __half t0 = __float2half_rn(a[j]);
        h0[j] = t0;
        h1[j] = __float2half_rn(a[j] - __half2float(t0));
    }
    const int e = i / D_MODEL;
    const int k = i % D_MODEL;
    const int c = k >> 5;
    const int kk = k & 31;
    __half* d0 = g_wp + ((size_t)(c * 2 + 0) * 64 + e) * 32 + kk;
    __half* d1 = g_wp + ((size_t)(c * 2 + 1) * 64 + e) * 32 + kk;
    *reinterpret_cast<uint2*>(d0) = *reinterpret_cast<uint2*>(h0);
    *reinterpret_cast<uint2*>(d1) = *reinterpret_cast<uint2*>(h1);
}

__device__ __forceinline__ uint32_t smem_u32(const void* p) {
    uint32_t a;
    asm("{ .reg .u64 t; cvta.to.shared.u64 t, %1; cvt.u32.u64 %0, t; }" : "=r"(a) : "l"(p));
    return a;
}
__device__ __forceinline__ void cp_async16(uint32_t dst, const void* src) {
    asm volatile("cp.async.cg.shared.global [%0], [%1], 16;" :: "r"(dst), "l"(src) : "memory");
}
#define CP_COMMIT() asm volatile("cp.async.commit_group;" ::: "memory")
#define CP_WAIT0()  asm volatile("cp.async.wait_group 0;" ::: "memory")

__global__ void __launch_bounds__(NTHREADS, 3) router_hsplit(
    const float* __restrict__ x,
    const float* __restrict__ bias,
    float* __restrict__ out,
    int n_rows)
{
    extern __shared__ __align__(16) __half smem[];

    const int tid = threadIdx.x;
    const int wid = tid >> 5;
    const int wm = wid & 3;
    const int wn = wid >> 2;
    const long long row0 = (long long)blockIdx.x * M_TILE;

    // x loader: 8 lanes cover one 128B line
    const int xr  = tid >> 3;            // base row 0..31 (sweeps +32)
    const int xc4 = (tid & 7) * 4;       // float col
    // W cp.async mapping: 2 rows per thread
    const int wr  = tid >> 2;            // 0..63 (sweeps +64)
    const int wsg = (tid & 3) * 8;       // 16B segment (halfs)

    const float* xb = x + row0 * D_MODEL;

    wmma::fragment<wmma::accumulator, 16, 16, 16, float> acc[2][2];
#pragma unroll
    for (int mt = 0; mt < 2; mt++)
#pragma unroll
        for (int nt = 0; nt < 2; nt++) wmma::fill_fragment(acc[mt][nt], 0.0f);

    float4 xv[4];

    auto loadg = [&](int c, int buf) {
        const int k0 = c * KC;
#pragma unroll
        for (int i = 0; i < 4; i++)
            xv[i] = *reinterpret_cast<const float4*>(
                xb + (long long)(xr + 32 * i) * D_MODEL + k0 + xc4);
        // W: cp.async, 128 rows (2lev x 64e), 64B each
        __half* Bb = smem + buf * SBUF_ELTS + 2 * A_ELTS;
        const __half* wsrc = g_wp + (size_t)c * 2 * NUM_EXPERTS * KC;
#pragma unroll
        for (int i = 0; i < 2; i++) {
            const int row = wr + 64 * i;      // row = lev*64 + e
            const int lev = row >> 6;
            const int e = row & 63;
            uint32_t dst = smem_u32(Bb + lev * B_ELTS + e * WS + wsg);
            cp_async16(dst, wsrc + row * 32 + wsg);
        }
        CP_COMMIT();
    };

    auto stores = [&](int buf) {
        __half* A0 = smem + buf * SBUF_ELTS;
        __half* A1 = A0 + A_ELTS;
#pragma unroll
        for (int i = 0; i < 4; i++) {
            float a0 = xv[i].x, a1 = xv[i].y, a2 = xv[i].z, a3 = xv[i].w;
            __half2 h0a = __floats2half2_rn(a0, a1);
            __half2 h0b = __floats2half2_rn(a2, a3);
            float r0 = a0 - __half2float(h0a.x);
            float r1 = a1 - __half2float(h0a.y);
            float r2 = a2 - __half2float(h0b.x);
            float r3 = a3 - __half2float(h0b.y);
            __half2 h1a = __floats2half2_rn(r0, r1);
            __half2 h1b = __floats2half2_rn(r2, r3);

            const int o = (xr + 32 * i) * AS + xc4;
            *reinterpret_cast<uint2*>(A0 + o) =
                make_uint2(*reinterpret_cast<uint32_t*>(&h0a), *reinterpret_cast<uint32_t*>(&h0b));
            *reinterpret_cast<uint2*>(A1 + o) =
                make_uint2(*reinterpret_cast<uint32_t*>(&h1a), *reinterpret_cast<uint32_t*>(&h1b));
        }
    };

    auto compute = [&](int buf) {
        const __half* A0 = smem + buf * SBUF_ELTS;
        const __half* A1 = A0 + A_ELTS;
        const __half* B0 = A0 + 2 * A_ELTS;
        const __half* B1 = B0 + B_ELTS;
#pragma unroll
        for (int ks = 0; ks < KC; ks += 16) {
            wmma::fragment<wmma::matrix_a, 16, 16, 16, __half, wmma::row_major> a0f[2], a1f[2];
            wmma::fragment<wmma::matrix_b, 16, 16, 16, __half, wmma::col_major> b0f[2], b1f[2];
#pragma unroll
            for (int mt = 0; mt < 2; mt++) {
                const int ro = (32 * wm + 16 * mt) * AS + ks;
                wmma::load_matrix_sync(a0f[mt], A0 + ro, AS);
                wmma::load_matrix_sync(a1f[mt], A1 + ro, AS);
            }
#pragma unroll
            for (int nt = 0; nt < 2; nt++) {
                const int co = (32 * wn + 16 * nt) * WS + ks;
                wmma::load_matrix_sync(b0f[nt], B0 + co, WS);
                wmma::load_matrix_sync(b1f[nt], B1 + co, WS);
            }
#pragma unroll
            for (int mt = 0; mt < 2; mt++)
#pragma unroll
                for (int nt = 0; nt < 2; nt++)
                    wmma::mma_sync(acc[mt][nt], a0f[mt], b0f[nt], acc[mt][nt]);
#pragma unroll
            for (int mt = 0; mt < 2; mt++)
#pragma unroll
                for (int nt = 0; nt < 2; nt++)
                    wmma::mma_sync(acc[mt][nt], a0f[mt], b1f[nt], acc[mt][nt]);
#pragma unroll
            for (int mt = 0; mt < 2; mt++)
#pragma unroll
                for (int nt = 0; nt < 2; nt++)
                    wmma::mma_sync(acc[mt][nt], a1f[mt], b0f[nt], acc[mt][nt]);
        }
    };

    // ---- prologue ----
    loadg(0, 0);
    stores(0);
    CP_WAIT0();
    __syncthreads();

#pragma unroll 1
    for (int c = 0; c < T_CHUNKS; ++c) {
        if (c + 1 < T_CHUNKS) loadg(c + 1, (c + 1) & 1);
        compute(c & 1);
        if (c + 1 < T_CHUNKS) stores((c + 1) & 1);
        CP_WAIT0();
        __syncthreads();
    }

    // ---- epilogue ----
    float* logits = reinterpret_cast<float*>(smem);
#pragma unroll
    for (int mt = 0; mt < 2; mt++)
#pragma unroll
        for (int nt = 0; nt < 2; nt++)
            wmma::store_matrix_sync(
                logits + (32 * wm + 16 * mt) * LSTRIDE + 32 * wn + 16 * nt,
                acc[mt][nt], LSTRIDE, wmma::mem_row_major);
    __syncthreads();

    if (tid < M_TILE) {
        const int r = tid;
        const float* lrow = logits + r * LSTRIDE;
        float v0 = -3.0e38f, v1 = -3.0e38f;
        int i0 = 0, i1 = 0;
#pragma unroll
        for (int e = 0; e < NUM_EXPERTS; e++) {
            float l = lrow[e] + __ldg(&bias[e]);
            if (l > v0) { v1 = v0; i1 = i0; v0 = l; i0 = e; }
            else if (l > v1) { v1 = l; i1 = e; }
        }
        float Z = 0.0f;
#pragma unroll
        for (int e = 0; e < NUM_EXPERTS; e++) {
            float l = lrow[e] + __ldg(&bias[e]);
            Z += __expf(l - v0);
        }
        float q0 = 1.0f / Z;
        float q1 = __expf(v1 - v0) / Z;
        float s = q0 + q1 + 1e-8f;
        long long gr = row0 + r;
        out[gr * 2 + 0] = q0 / s;
        out[gr * 2 + 1] = q1 / s;
        float* ido = out + (long long)n_rows * 2;
        ido[gr * 2 + 0] = (float)i0;
        ido[gr * 2 + 1] = (float)i1;
    }
}

extern "C" void kernel_launch(void* const* d_in, const int* in_sizes, int n_in,
                              void* d_out, int out_size) {
    const float* x    = (const float*)d_in[0];
    const float* gw   = (const float*)d_in[1];
    const float* bias = (const float*)d_in[2];
    float* out = (float*)d_out;
    int n_rows = in_sizes[0] / D_MODEL;   // 32768

    cudaFuncSetAttribute(router_hsplit, cudaFuncAttributeMaxDynamicSharedMemorySize, SMEM_BYTES);

    prep_w<<<(NUM_EXPERTS * D_MODEL / 4) / 256, 256>>>(gw);
    router_hsplit<<<n_rows / M_TILE, NTHREADS, SMEM_BYTES>>>(x, bias, out, n_rows);
}